// round 10
// baseline (speedup 1.0000x reference)
#include <cuda_runtime.h>

typedef unsigned long long u64;

#define Bn 16
#define Hn 1024
#define Tn 4096
#define CDn 8
#define CSn 1024

#define THREADS 256
#define TT 128
#define NBLK 512          // 16 batches * 32 tiles
#define HC 16             // h per staged tile
#define NTILES (Hn / HC)  // 64

#define OUT_N ((size_t)Bn * Hn * Tn)
#define LOSS_OFF (OUT_N)
#define IDX_OFF (OUT_N + 2)
#define PROJ_OFF (OUT_N + 2 + (size_t)Bn * Tn)

__device__ float g_losspart[NBLK];
__device__ unsigned int g_count;

__device__ __forceinline__ u64 pack2(float x, float y) {
    u64 r; asm("mov.b64 %0, {%1,%2};" : "=l"(r) : "f"(x), "f"(y)); return r;
}
__device__ __forceinline__ void unpack2(u64 v, float& x, float& y) {
    asm("mov.b64 {%0,%1}, %2;" : "=f"(x), "=f"(y) : "l"(v));
}
__device__ __forceinline__ u64 ffma2(u64 a, u64 b, u64 c) {
    u64 d; asm("fma.rn.f32x2 %0, %1, %2, %3;" : "=l"(d) : "l"(a), "l"(b), "l"(c)); return d;
}
__device__ __forceinline__ void pfL2(const void* p) {
    asm volatile("prefetch.global.L2 [%0];" :: "l"(p));
}

// smem float layout:
//   A     [0,8192)       : ws(dup-free [h][d]) / cbs / wdup d0-3
//   Bz    [8192,16384)   : xdup tiles (2 x 4096) / cb2s(1024) / wdup d4-7
//   xfer  [16384,17408)  : proj handoff (phase1-2) / bos (phase3)
//   sbestg[17408,17792)  float2[3][64]
//   sidxg [17792,18176)  int2[3][64]
//   sidxf [18176,18304)  int2[64]
//   wsum  [18304,18312)
#define SMEM_FLOATS 18312
extern __shared__ float smem[];

__global__ __launch_bounds__(THREADS, 3) void main_kernel(
    const float* __restrict__ hid,   // [B,H,T]
    const float* __restrict__ w_in,  // [CD,H]
    const float* __restrict__ b_in,  // [CD]
    const float* __restrict__ w_out, // [H,CD]
    const float* __restrict__ b_out, // [H]
    const float* __restrict__ cb,    // [CS,CD]
    float* __restrict__ dout)
{
    float*  A      = smem;
    float*  Bz     = smem + 8192;
    float*  xfer   = smem + 16384;
    float2* sbestg = reinterpret_cast<float2*>(smem + 17408);
    int2*   sidxg  = reinterpret_cast<int2*>(smem + 17792);
    int2*   sidxf  = reinterpret_cast<int2*>(smem + 18176);
    float*  wsum   = smem + 18304;
    __shared__ unsigned int s_is_last;

    const int tid = threadIdx.x;
    const int blk = blockIdx.x;
    const int b   = blk >> 5;
    const int t0  = (blk & 31) << 7;

    // ---- fill ws[h][d] from w_in[d][h] into A -----------------------------
#pragma unroll
    for (int k = 0; k < 32; k++) {
        int idx = tid + THREADS * k;
        int d = idx >> 10, h = idx & 1023;
        A[h * CDn + d] = w_in[idx];
    }

    // ---- stage tile 0 (regs), then STS dup --------------------------------
    const float* xsrc = hid + (size_t)b * Hn * Tn + t0;
    u64* xb0 = reinterpret_cast<u64*>(Bz);
    u64* xb1 = reinterpret_cast<u64*>(Bz + 4096);

    float4 st[2];
#pragma unroll
    for (int k = 0; k < 2; k++) {
        int f = tid + THREADS * k;
        int hl = f >> 5, tq = f & 31;
        st[k] = __ldcs(reinterpret_cast<const float4*>(xsrc + (size_t)hl * Tn + 4 * tq));
    }
#pragma unroll
    for (int k = 0; k < 2; k++) {
        int f = tid + THREADS * k;
        int hl = f >> 5, tq = f & 31;
        u64* dst = xb0 + hl * 128 + 4 * tq;
        ulonglong2 lo, hi;
        lo.x = pack2(st[k].x, st[k].x); lo.y = pack2(st[k].y, st[k].y);
        hi.x = pack2(st[k].z, st[k].z); hi.y = pack2(st[k].w, st[k].w);
        *reinterpret_cast<ulonglong2*>(dst)     = lo;
        *reinterpret_cast<ulonglong2*>(dst + 2) = hi;
    }
    __syncthreads();

    // ================= Phase 1: proj, staged double-buffer ==================
    const int half = tid >> 7;        // 0: d0-3, 1: d4-7
    const int tcol = tid & 127;
    const u64* A64c = reinterpret_cast<const u64*>(A);
    u64 acc0 = 0ULL, acc1 = 0ULL;

    for (int tile = 0; tile < NTILES; tile++) {
        // load next tile into regs (latency overlapped with compute)
        if (tile + 1 < NTILES) {
#pragma unroll
            for (int k = 0; k < 2; k++) {
                int f = tid + THREADS * k;
                int hl = f >> 5, tq = f & 31;
                st[k] = __ldcs(reinterpret_cast<const float4*>(
                    xsrc + (size_t)((tile + 1) * HC + hl) * Tn + 4 * tq));
            }
        }
        // L2 prefetch 2 tiles ahead (64 lines per tile)
        if (tid < 64 && tile + 2 < NTILES) {
            int hl = tid >> 2, q = tid & 3;
            pfL2(xsrc + (size_t)((tile + 2) * HC + hl) * Tn + 32 * q);
        }

        const u64* xb = (tile & 1) ? xb1 : xb0;
#pragma unroll
        for (int hh = 0; hh < HC; hh++) {
            int h = tile * HC + hh;
            u64 xd = xb[hh * 128 + tcol];
            ulonglong2 w = *reinterpret_cast<const ulonglong2*>(A64c + h * 4 + 2 * half);
            acc0 = ffma2(w.x, xd, acc0);
            acc1 = ffma2(w.y, xd, acc1);
        }

        if (tile + 1 < NTILES) {
            u64* xbn = (tile & 1) ? xb0 : xb1;
#pragma unroll
            for (int k = 0; k < 2; k++) {
                int f = tid + THREADS * k;
                int hl = f >> 5, tq = f & 31;
                u64* dst = xbn + hl * 128 + 4 * tq;
                ulonglong2 lo, hi;
                lo.x = pack2(st[k].x, st[k].x); lo.y = pack2(st[k].y, st[k].y);
                hi.x = pack2(st[k].z, st[k].z); hi.y = pack2(st[k].w, st[k].w);
                *reinterpret_cast<ulonglong2*>(dst)     = lo;
                *reinterpret_cast<ulonglong2*>(dst + 2) = hi;
            }
        }
        __syncthreads();
    }

    // proj tail: add bias, hand off + gmem store
    {
        float p[4];
        unpack2(acc0, p[0], p[1]);
        unpack2(acc1, p[2], p[3]);
#pragma unroll
        for (int d = 0; d < 4; d++) {
            float v = __fadd_rn(p[d], __ldg(b_in + 4 * half + d));
            xfer[tcol * CDn + 4 * half + d] = v;
            __stcs(dout + PROJ_OFF + ((size_t)b * CDn + 4 * half + d) * Tn + (t0 + tcol), v);
        }
    }

    // ---- normalized codebook into A (cbs) + Bz[0:1024] (cb2s) -------------
    float* cbs  = A;
    float* cb2s = Bz;
#pragma unroll
    for (int k = 0; k < 4; k++) {
        int j = tid + THREADS * k;
        const float4* cr = reinterpret_cast<const float4*>(cb + j * CDn);
        float4 ca = __ldg(cr), cbv4 = __ldg(cr + 1);
        float v[CDn] = {ca.x, ca.y, ca.z, ca.w, cbv4.x, cbv4.y, cbv4.z, cbv4.w};
        float s = 0.f;
#pragma unroll
        for (int d = 0; d < CDn; d++) s = __fadd_rn(s, __fmul_rn(v[d], v[d]));
        float m = fmaxf(__fsqrt_rn(s), 1e-12f);
        float cd[CDn];
        float s2 = 0.f;
#pragma unroll
        for (int d = 0; d < CDn; d++) {
            cd[d] = __fdiv_rn(v[d], m);
            s2 = __fadd_rn(s2, __fmul_rn(cd[d], cd[d]));
        }
        float4* dst = reinterpret_cast<float4*>(cbs + j * CDn);
        dst[0] = make_float4(cd[0], cd[1], cd[2], cd[3]);
        dst[1] = make_float4(cd[4], cd[5], cd[6], cd[7]);
        cb2s[j] = s2;
    }
    __syncthreads();

    // ================= Phase 2: argmax. 2 t/thread, j split 4-way ===========
    const int pr  = tid & 63;
    const int grp = tid >> 6;

    float l20, l21;
    u64 ed0[4], ed1[4];
    float p0[CDn], p1[CDn];
    {
        const float4* x0 = reinterpret_cast<const float4*>(xfer + (2 * pr) * CDn);
        const float4* x1 = reinterpret_cast<const float4*>(xfer + (2 * pr + 1) * CDn);
        float4 a0 = x0[0], a1 = x0[1], c0 = x1[0], c1 = x1[1];
        p0[0]=a0.x; p0[1]=a0.y; p0[2]=a0.z; p0[3]=a0.w;
        p0[4]=a1.x; p0[5]=a1.y; p0[6]=a1.z; p0[7]=a1.w;
        p1[0]=c0.x; p1[1]=c0.y; p1[2]=c0.z; p1[3]=c0.w;
        p1[4]=c1.x; p1[5]=c1.y; p1[6]=c1.z; p1[7]=c1.w;

        float l2r0 = 0.f, l2r1 = 0.f;
#pragma unroll
        for (int d = 0; d < CDn; d++) {
            l2r0 = __fadd_rn(l2r0, __fmul_rn(p0[d], p0[d]));
            l2r1 = __fadd_rn(l2r1, __fmul_rn(p1[d], p1[d]));
        }
        float den0 = fmaxf(__fsqrt_rn(l2r0), 1e-12f);
        float den1 = fmaxf(__fsqrt_rn(l2r1), 1e-12f);
        float e0[CDn], e1[CDn];
        l20 = 0.f; l21 = 0.f;
#pragma unroll
        for (int d = 0; d < CDn; d++) {
            e0[d] = __fdiv_rn(p0[d], den0);
            e1[d] = __fdiv_rn(p1[d], den1);
            l20 = __fadd_rn(l20, __fmul_rn(e0[d], e0[d]));
            l21 = __fadd_rn(l21, __fmul_rn(e1[d], e1[d]));
        }
#pragma unroll
        for (int q = 0; q < 4; q++) {
            ed0[q] = pack2(e0[2 * q], e0[2 * q + 1]);
            ed1[q] = pack2(e1[2 * q], e1[2 * q + 1]);
        }
    }

    const int jstart = grp << 8;
    float best0 = -3.402823466e38f, best1 = -3.402823466e38f;
    int i0 = jstart, i1 = jstart;
#pragma unroll 2
    for (int j = jstart; j < jstart + 256; j++) {
        const ulonglong2* cr = reinterpret_cast<const ulonglong2*>(cbs + j * CDn);
        ulonglong2 ca = cr[0], cbp = cr[1];
        float cb2 = cb2s[j];

        u64 a = ffma2(ed0[0], ca.x, 0ULL);
        a = ffma2(ed0[1], ca.y, a); a = ffma2(ed0[2], cbp.x, a); a = ffma2(ed0[3], cbp.y, a);
        float alo, ahi; unpack2(a, alo, ahi);
        float dot0 = __fadd_rn(alo, ahi);
        float s0 = __fsub_rn(cb2, __fmaf_rn(-2.f, dot0, l20));
        if (s0 > best0) { best0 = s0; i0 = j; }

        u64 bq = ffma2(ed1[0], ca.x, 0ULL);
        bq = ffma2(ed1[1], ca.y, bq); bq = ffma2(ed1[2], cbp.x, bq); bq = ffma2(ed1[3], cbp.y, bq);
        float blo, bhi; unpack2(bq, blo, bhi);
        float dot1 = __fadd_rn(blo, bhi);
        float s1 = __fsub_rn(cb2, __fmaf_rn(-2.f, dot1, l21));
        if (s1 > best1) { best1 = s1; i1 = j; }
    }
    if (grp) {
        sbestg[(grp - 1) * 64 + pr] = make_float2(best0, best1);
        sidxg[(grp - 1) * 64 + pr]  = make_int2(i0, i1);
    }
    __syncthreads();

    // ---- fill wdup (A: d0-3, Bz: d4-7) + bos(xfer) + g0 combine/epilogue ---
    {
        const float4* wov = reinterpret_cast<const float4*>(w_out);
        u64* A64 = reinterpret_cast<u64*>(A);
        u64* B64 = reinterpret_cast<u64*>(Bz);
#pragma unroll
        for (int k = 0; k < 8; k++) {
            int i = tid + THREADS * k;               // float4 index in [0,2048)
            float4 wq = __ldg(wov + i);
            int h = i >> 1, hf = i & 1;
            u64* dst = (hf ? B64 : A64) + h * 4;
            ulonglong2 lo, hi;
            lo.x = pack2(wq.x, wq.x); lo.y = pack2(wq.y, wq.y);
            hi.x = pack2(wq.z, wq.z); hi.y = pack2(wq.w, wq.w);
            *reinterpret_cast<ulonglong2*>(dst)     = lo;
            *reinterpret_cast<ulonglong2*>(dst + 2) = hi;
        }
#pragma unroll
        for (int k = 0; k < 4; k++) {
            int i = tid + THREADS * k;
            xfer[i] = b_out[i];
        }
    }

    if (grp == 0) {
        // combine ascending-j: strict > keeps first max (exact)
#pragma unroll
        for (int g = 0; g < 3; g++) {
            float2 bb = sbestg[g * 64 + pr];
            int2   ii = sidxg[g * 64 + pr];
            if (bb.x > best0) { best0 = bb.x; i0 = ii.x; }
            if (bb.y > best1) { best1 = bb.y; i1 = ii.y; }
        }
        sidxf[pr] = make_int2(i0, i1);
        __stcs(reinterpret_cast<float2*>(dout + IDX_OFF + (size_t)b * Tn + t0 + 2 * pr),
               make_float2((float)i0, (float)i1));

        const float4* cbv = reinterpret_cast<const float4*>(cb);
        float4 qa0 = __ldg(cbv + i0 * 2), qb0 = __ldg(cbv + i0 * 2 + 1);
        float4 qa1 = __ldg(cbv + i1 * 2), qb1 = __ldg(cbv + i1 * 2 + 1);
        float q0[CDn] = {qa0.x, qa0.y, qa0.z, qa0.w, qb0.x, qb0.y, qb0.z, qb0.w};
        float q1[CDn] = {qa1.x, qa1.y, qa1.z, qa1.w, qb1.x, qb1.y, qb1.z, qb1.w};

        float ls = 0.f;
#pragma unroll
        for (int d = 0; d < CDn; d++) {
            float a = p0[d] - q0[d]; ls = __fmaf_rn(a, a, ls);
            float c = p1[d] - q1[d]; ls = __fmaf_rn(c, c, ls);
        }
#pragma unroll
        for (int o = 16; o; o >>= 1) ls += __shfl_xor_sync(0xFFFFFFFFu, ls, o);
        if ((tid & 31) == 0) wsum[tid >> 5] = ls;
    }
    __syncthreads();
    if (tid == 0) g_losspart[blk] = wsum[0] + wsum[1];

    // ================= Phase 3: out. 4 t/thread t-packed, h split 8-way =====
    {
        const int pr3  = tid & 31;
        const int grp3 = tid >> 5;
        int2 j01 = sidxf[2 * pr3], j23 = sidxf[2 * pr3 + 1];
        const float4* cbv = reinterpret_cast<const float4*>(cb);
        float4 qA0 = __ldg(cbv + j01.x * 2), qA1 = __ldg(cbv + j01.x * 2 + 1);
        float4 qB0 = __ldg(cbv + j01.y * 2), qB1 = __ldg(cbv + j01.y * 2 + 1);
        float4 qC0 = __ldg(cbv + j23.x * 2), qC1 = __ldg(cbv + j23.x * 2 + 1);
        float4 qD0 = __ldg(cbv + j23.y * 2), qD1 = __ldg(cbv + j23.y * 2 + 1);

        u64 qp01[8], qp23[8];
        qp01[0] = pack2(qA0.x, qB0.x); qp01[1] = pack2(qA0.y, qB0.y);
        qp01[2] = pack2(qA0.z, qB0.z); qp01[3] = pack2(qA0.w, qB0.w);
        qp01[4] = pack2(qA1.x, qB1.x); qp01[5] = pack2(qA1.y, qB1.y);
        qp01[6] = pack2(qA1.z, qB1.z); qp01[7] = pack2(qA1.w, qB1.w);
        qp23[0] = pack2(qC0.x, qD0.x); qp23[1] = pack2(qC0.y, qD0.y);
        qp23[2] = pack2(qC0.z, qD0.z); qp23[3] = pack2(qC0.w, qD0.w);
        qp23[4] = pack2(qC1.x, qD1.x); qp23[5] = pack2(qC1.y, qD1.y);
        qp23[6] = pack2(qC1.z, qD1.z); qp23[7] = pack2(qC1.w, qD1.w);

        const u64* A64c2 = reinterpret_cast<const u64*>(A);
        const u64* B64c2 = reinterpret_cast<const u64*>(Bz);
        float* outbase = dout + (size_t)b * Hn * Tn + (t0 + 4 * pr3);
        const int hbase = grp3 << 7;
#pragma unroll 4
        for (int hh = 0; hh < 128; hh++) {
            int h = hbase + hh;
            ulonglong2 w0 = *reinterpret_cast<const ulonglong2*>(A64c2 + h * 4);
            ulonglong2 w1 = *reinterpret_cast<const ulonglong2*>(A64c2 + h * 4 + 2);
            ulonglong2 w2 = *reinterpret_cast<const ulonglong2*>(B64c2 + h * 4);
            ulonglong2 w3 = *reinterpret_cast<const ulonglong2*>(B64c2 + h * 4 + 2);
            float bo = xfer[h];
            u64 bd = pack2(bo, bo);

            u64 a = ffma2(qp01[0], w0.x, bd);
            a = ffma2(qp01[1], w0.y, a); a = ffma2(qp01[2], w1.x, a);
            a = ffma2(qp01[3], w1.y, a); a = ffma2(qp01[4], w2.x, a);
            a = ffma2(qp01[5], w2.y, a); a = ffma2(qp01[6], w3.x, a);
            a = ffma2(qp01[7], w3.y, a);

            u64 c = ffma2(qp23[0], w0.x, bd);
            c = ffma2(qp23[1], w0.y, c); c = ffma2(qp23[2], w1.x, c);
            c = ffma2(qp23[3], w1.y, c); c = ffma2(qp23[4], w2.x, c);
            c = ffma2(qp23[5], w2.y, c); c = ffma2(qp23[6], w3.x, c);
            c = ffma2(qp23[7], w3.y, c);

            float a0f, a1f, c0f, c1f;
            unpack2(a, a0f, a1f);
            unpack2(c, c0f, c1f);
            __stcs(reinterpret_cast<float4*>(outbase + (size_t)h * Tn),
                   make_float4(a0f, a1f, c0f, c1f));
        }
    }

    // ---- last block finalizes loss mean ------------------------------------
    __syncthreads();
    if (tid == 0) {
        __threadfence();
        unsigned int c = atomicAdd(&g_count, 1u);
        s_is_last = (c == NBLK - 1) ? 1u : 0u;
        if (s_is_last) g_count = 0;
    }
    __syncthreads();
    if (s_is_last) {
        float v = __ldcg(g_losspart + tid) + __ldcg(g_losspart + tid + THREADS);
#pragma unroll
        for (int o = 16; o; o >>= 1) v += __shfl_xor_sync(0xFFFFFFFFu, v, o);
        __syncthreads();
        if ((tid & 31) == 0) sbestg[tid >> 5].x = v;
        __syncthreads();
        if (tid == 0) {
            float tot = 0.f;
#pragma unroll
            for (int w = 0; w < THREADS / 32; w++) tot += sbestg[w].x;
            float mean = tot * (1.0f / (float)(Bn * CDn * Tn));
            dout[LOSS_OFF]     = mean;
            dout[LOSS_OFF + 1] = mean;
        }
    }
}

// ---------------------------------------------------------------------------
extern "C" void kernel_launch(void* const* d_in, const int* in_sizes, int n_in,
                              void* d_out, int out_size) {
    const float* hid   = (const float*)d_in[0];
    const float* w_in  = (const float*)d_in[1];
    const float* b_in  = (const float*)d_in[2];
    const float* w_out = (const float*)d_in[3];
    const float* b_out = (const float*)d_in[4];
    const float* cb    = (const float*)d_in[5];
    float* dout = (float*)d_out;

    const int smem_bytes = SMEM_FLOATS * 4;  // 73248 B
    cudaFuncSetAttribute(main_kernel, cudaFuncAttributeMaxDynamicSharedMemorySize, smem_bytes);

    main_kernel<<<NBLK, THREADS, smem_bytes>>>(hid, w_in, b_in, w_out, b_out, cb, dout);
}

// round 11
// speedup vs baseline: 1.2242x; 1.2242x over previous
#include <cuda_runtime.h>

typedef unsigned long long u64;

#define Bn 16
#define Hn 1024
#define Tn 4096
#define CDn 8
#define CSn 1024

#define THREADS 256
#define TT 128
#define TILES_PER_B (Tn / TT)        // 32
#define NBLK (Bn * TILES_PER_B)      // 512

#define OUT_N ((size_t)Bn * Hn * Tn)
#define LOSS_OFF (OUT_N)
#define IDX_OFF (OUT_N + 2)
#define PROJ_OFF (OUT_N + 2 + (size_t)Bn * Tn)

__device__ float g_losspart[NBLK];
__device__ unsigned int g_count;

__device__ __forceinline__ u64 pack2(float x, float y) {
    u64 r; asm("mov.b64 %0, {%1,%2};" : "=l"(r) : "f"(x), "f"(y)); return r;
}
__device__ __forceinline__ void unpack2(u64 v, float& x, float& y) {
    asm("mov.b64 {%0,%1}, %2;" : "=f"(x), "=f"(y) : "l"(v));
}
__device__ __forceinline__ u64 ffma2(u64 a, u64 b, u64 c) {
    u64 d; asm("fma.rn.f32x2 %0, %1, %2, %3;" : "=l"(d) : "l"(a), "l"(b), "l"(c)); return d;
}
__device__ __forceinline__ void pfL2(const void* p) {
    asm volatile("prefetch.global.L2 [%0];" :: "l"(p));
}

// smem float layout:
//   [0,9216)      buf : ws(8192) | cbs(8192)+cb2s(1024) | wos(8192)+bos(1024)
//   [9216,10240)  xfer : proj handoff, 128 t x 8 d
//   [10240,10624) sbestg : float2[3][64]
//   [10624,11008) sidxg  : int2[3][64]
//   [11008,11136) sidxf  : int2[64]  (combined winners)
//   [11136,11138) wsum
#define SMEM_FLOATS 11144
extern __shared__ float smem[];

__global__ __launch_bounds__(THREADS, 4) void main_kernel(
    const float* __restrict__ hid,   // [B,H,T]
    const float* __restrict__ w_in,  // [CD,H]
    const float* __restrict__ b_in,  // [CD]
    const float* __restrict__ w_out, // [H,CD]
    const float* __restrict__ b_out, // [H]
    const float* __restrict__ cb,    // [CS,CD]
    float* __restrict__ dout)
{
    float*  buf    = smem;
    float*  xfer   = smem + 9216;
    float2* sbestg = reinterpret_cast<float2*>(smem + 10240);
    int2*   sidxg  = reinterpret_cast<int2*>(smem + 10624);
    int2*   sidxf  = reinterpret_cast<int2*>(smem + 11008);
    float*  wsum   = smem + 11136;
    __shared__ unsigned int s_is_last;

    const int tid = threadIdx.x;
    const int blk = blockIdx.x;
    const int b   = blk >> 5;
    const int t0  = (blk & 31) << 7;

    // ---- fill ws[h][d] from w_in[d][h] ------------------------------------
#pragma unroll
    for (int k = 0; k < 32; k++) {
        int idx = tid + THREADS * k;
        int d = idx >> 10, h = idx & 1023;
        buf[h * CDn + d] = w_in[idx];
    }
    __syncthreads();

    // ================= Phase 1: proj. 2 threads per t (4 d each) ===========
    {
        const int half = tid >> 7;        // 0: d0-3, 1: d4-7
        const int tcol = tid & 127;
        const bool dopf = (half == 0);    // warp-uniform
        u64 acc0 = 0ULL, acc1 = 0ULL;
        const float* xp = hid + (size_t)b * Hn * Tn + (t0 + tcol);
        const float* wbase = buf + 4 * half;

#define PF 32
#pragma unroll 8
        for (int h = 0; h < Hn - PF; h++) {
            if (dopf) pfL2(xp + (size_t)(h + PF) * Tn);
            float x = __ldg(xp + (size_t)h * Tn);     // default cache: keep L1 hit for 2nd half
            u64 xd = pack2(x, x);
            ulonglong2 w = *reinterpret_cast<const ulonglong2*>(wbase + h * CDn);
            acc0 = ffma2(w.x, xd, acc0);
            acc1 = ffma2(w.y, xd, acc1);
        }
#pragma unroll 8
        for (int h = Hn - PF; h < Hn; h++) {
            float x = __ldg(xp + (size_t)h * Tn);
            u64 xd = pack2(x, x);
            ulonglong2 w = *reinterpret_cast<const ulonglong2*>(wbase + h * CDn);
            acc0 = ffma2(w.x, xd, acc0);
            acc1 = ffma2(w.y, xd, acc1);
        }
#undef PF
        float p[4];
        unpack2(acc0, p[0], p[1]);
        unpack2(acc1, p[2], p[3]);
#pragma unroll
        for (int d = 0; d < 4; d++) {
            float v = __fadd_rn(p[d], __ldg(b_in + 4 * half + d));
            xfer[tcol * CDn + 4 * half + d] = v;
            __stcs(dout + PROJ_OFF + ((size_t)b * CDn + 4 * half + d) * Tn + (t0 + tcol), v);
        }
    }
    __syncthreads();

    // ---- normalized codebook into cbs/cb2s (identical math) ----------------
    float* cbs  = buf;
    float* cb2s = buf + CSn * CDn;
#pragma unroll
    for (int k = 0; k < 4; k++) {
        int j = tid + THREADS * k;
        const float4* cr = reinterpret_cast<const float4*>(cb + j * CDn);
        float4 ca = __ldg(cr), cbv4 = __ldg(cr + 1);
        float v[CDn] = {ca.x, ca.y, ca.z, ca.w, cbv4.x, cbv4.y, cbv4.z, cbv4.w};
        float s = 0.f;
#pragma unroll
        for (int d = 0; d < CDn; d++) s = __fadd_rn(s, __fmul_rn(v[d], v[d]));
        float m = fmaxf(__fsqrt_rn(s), 1e-12f);
        float cd[CDn];
        float s2 = 0.f;
#pragma unroll
        for (int d = 0; d < CDn; d++) {
            cd[d] = __fdiv_rn(v[d], m);
            s2 = __fadd_rn(s2, __fmul_rn(cd[d], cd[d]));
        }
        float4* dst = reinterpret_cast<float4*>(cbs + j * CDn);
        dst[0] = make_float4(cd[0], cd[1], cd[2], cd[3]);
        dst[1] = make_float4(cd[4], cd[5], cd[6], cd[7]);
        cb2s[j] = s2;
    }
    __syncthreads();

    // ================= Phase 2: argmax. 2 t/thread, j split 4-way ===========
    const int pr  = tid & 63;
    const int grp = tid >> 6;

    float l20, l21;
    u64 ed0[4], ed1[4];
    float p0[CDn], p1[CDn];
    {
        const float4* x0 = reinterpret_cast<const float4*>(xfer + (2 * pr) * CDn);
        const float4* x1 = reinterpret_cast<const float4*>(xfer + (2 * pr + 1) * CDn);
        float4 a0 = x0[0], a1 = x0[1], c0 = x1[0], c1 = x1[1];
        p0[0]=a0.x; p0[1]=a0.y; p0[2]=a0.z; p0[3]=a0.w;
        p0[4]=a1.x; p0[5]=a1.y; p0[6]=a1.z; p0[7]=a1.w;
        p1[0]=c0.x; p1[1]=c0.y; p1[2]=c0.z; p1[3]=c0.w;
        p1[4]=c1.x; p1[5]=c1.y; p1[6]=c1.z; p1[7]=c1.w;

        float l2r0 = 0.f, l2r1 = 0.f;
#pragma unroll
        for (int d = 0; d < CDn; d++) {
            l2r0 = __fadd_rn(l2r0, __fmul_rn(p0[d], p0[d]));
            l2r1 = __fadd_rn(l2r1, __fmul_rn(p1[d], p1[d]));
        }
        float den0 = fmaxf(__fsqrt_rn(l2r0), 1e-12f);
        float den1 = fmaxf(__fsqrt_rn(l2r1), 1e-12f);
        float e0[CDn], e1[CDn];
        l20 = 0.f; l21 = 0.f;
#pragma unroll
        for (int d = 0; d < CDn; d++) {
            e0[d] = __fdiv_rn(p0[d], den0);
            e1[d] = __fdiv_rn(p1[d], den1);
            l20 = __fadd_rn(l20, __fmul_rn(e0[d], e0[d]));
            l21 = __fadd_rn(l21, __fmul_rn(e1[d], e1[d]));
        }
#pragma unroll
        for (int q = 0; q < 4; q++) {
            ed0[q] = pack2(e0[2 * q], e0[2 * q + 1]);
            ed1[q] = pack2(e1[2 * q], e1[2 * q + 1]);
        }
    }

    const int jstart = grp << 8;
    float best0 = -3.402823466e38f, best1 = -3.402823466e38f;
    int i0 = jstart, i1 = jstart;
#pragma unroll 2
    for (int j = jstart; j < jstart + 256; j += 2) {
        // batched loads for j and j+1 (values identical; update order j -> j+1)
        const ulonglong2* crA = reinterpret_cast<const ulonglong2*>(cbs + j * CDn);
        ulonglong2 caA = crA[0], cbA = crA[1];
        ulonglong2 caB = crA[2], cbB = crA[3];
        float2 cb2p = *reinterpret_cast<const float2*>(cb2s + j);

        // ---- j ----
        {
            u64 a = ffma2(ed0[0], caA.x, 0ULL);
            a = ffma2(ed0[1], caA.y, a); a = ffma2(ed0[2], cbA.x, a); a = ffma2(ed0[3], cbA.y, a);
            float alo, ahi; unpack2(a, alo, ahi);
            float dot0 = __fadd_rn(alo, ahi);
            float s0 = __fsub_rn(cb2p.x, __fmaf_rn(-2.f, dot0, l20));
            if (s0 > best0) { best0 = s0; i0 = j; }

            u64 bq = ffma2(ed1[0], caA.x, 0ULL);
            bq = ffma2(ed1[1], caA.y, bq); bq = ffma2(ed1[2], cbA.x, bq); bq = ffma2(ed1[3], cbA.y, bq);
            float blo, bhi; unpack2(bq, blo, bhi);
            float dot1 = __fadd_rn(blo, bhi);
            float s1 = __fsub_rn(cb2p.x, __fmaf_rn(-2.f, dot1, l21));
            if (s1 > best1) { best1 = s1; i1 = j; }
        }
        // ---- j + 1 ----
        {
            u64 a = ffma2(ed0[0], caB.x, 0ULL);
            a = ffma2(ed0[1], caB.y, a); a = ffma2(ed0[2], cbB.x, a); a = ffma2(ed0[3], cbB.y, a);
            float alo, ahi; unpack2(a, alo, ahi);
            float dot0 = __fadd_rn(alo, ahi);
            float s0 = __fsub_rn(cb2p.y, __fmaf_rn(-2.f, dot0, l20));
            if (s0 > best0) { best0 = s0; i0 = j + 1; }

            u64 bq = ffma2(ed1[0], caB.x, 0ULL);
            bq = ffma2(ed1[1], caB.y, bq); bq = ffma2(ed1[2], cbB.x, bq); bq = ffma2(ed1[3], cbB.y, bq);
            float blo, bhi; unpack2(bq, blo, bhi);
            float dot1 = __fadd_rn(blo, bhi);
            float s1 = __fsub_rn(cb2p.y, __fmaf_rn(-2.f, dot1, l21));
            if (s1 > best1) { best1 = s1; i1 = j + 1; }
        }
    }
    if (grp) {
        sbestg[(grp - 1) * 64 + pr] = make_float2(best0, best1);
        sidxg[(grp - 1) * 64 + pr]  = make_int2(i0, i1);
    }
    __syncthreads();

    // ---- fill wos/bos (all threads, overwrites cbs) + g0 combine/epilogue --
    float* wos = buf;
    float* bos = buf + Hn * CDn;
    {
        const float4* wov = reinterpret_cast<const float4*>(w_out);
        float4* wod = reinterpret_cast<float4*>(wos);
#pragma unroll
        for (int k = 0; k < 8; k++) {
            int idx = tid + THREADS * k;
            wod[idx] = __ldg(wov + idx);
        }
#pragma unroll
        for (int k = 0; k < 4; k++) {
            int idx = tid + THREADS * k;
            bos[idx] = b_out[idx];
        }
    }

    if (grp == 0) {
        // combine in ascending-j group order: strict > keeps first max (exact)
#pragma unroll
        for (int g = 0; g < 3; g++) {
            float2 bb = sbestg[g * 64 + pr];
            int2   ii = sidxg[g * 64 + pr];
            if (bb.x > best0) { best0 = bb.x; i0 = ii.x; }
            if (bb.y > best1) { best1 = bb.y; i1 = ii.y; }
        }
        sidxf[pr] = make_int2(i0, i1);
        __stcs(reinterpret_cast<float2*>(dout + IDX_OFF + (size_t)b * Tn + t0 + 2 * pr),
               make_float2((float)i0, (float)i1));

        // loss partial: p kept in regs, q from codebook
        const float4* cbv = reinterpret_cast<const float4*>(cb);
        float4 qa0 = __ldg(cbv + i0 * 2), qb0 = __ldg(cbv + i0 * 2 + 1);
        float4 qa1 = __ldg(cbv + i1 * 2), qb1 = __ldg(cbv + i1 * 2 + 1);
        float q0[CDn] = {qa0.x, qa0.y, qa0.z, qa0.w, qb0.x, qb0.y, qb0.z, qb0.w};
        float q1[CDn] = {qa1.x, qa1.y, qa1.z, qa1.w, qb1.x, qb1.y, qb1.z, qb1.w};

        float ls = 0.f;
#pragma unroll
        for (int d = 0; d < CDn; d++) {
            float a = p0[d] - q0[d]; ls = __fmaf_rn(a, a, ls);
            float c = p1[d] - q1[d]; ls = __fmaf_rn(c, c, ls);
        }
#pragma unroll
        for (int o = 16; o; o >>= 1) ls += __shfl_xor_sync(0xFFFFFFFFu, ls, o);
        if ((tid & 31) == 0) wsum[tid >> 5] = ls;
    }
    __syncthreads();
    if (tid == 0) g_losspart[blk] = wsum[0] + wsum[1];

    // ================= Phase 3: out. 2 t/thread, h split 4-way ==============
    {
        int2 ji = sidxf[pr];
        const float4* cbv = reinterpret_cast<const float4*>(cb);
        float4 qa0 = __ldg(cbv + ji.x * 2), qb0 = __ldg(cbv + ji.x * 2 + 1);
        float4 qa1 = __ldg(cbv + ji.y * 2), qb1 = __ldg(cbv + ji.y * 2 + 1);

        u64 qp0[4], qp1[4];
        qp0[0] = pack2(qa0.x, qa0.y); qp0[1] = pack2(qa0.z, qa0.w);
        qp0[2] = pack2(qb0.x, qb0.y); qp0[3] = pack2(qb0.z, qb0.w);
        qp1[0] = pack2(qa1.x, qa1.y); qp1[1] = pack2(qa1.z, qa1.w);
        qp1[2] = pack2(qb1.x, qb1.y); qp1[3] = pack2(qb1.z, qb1.w);

        float* outbase = dout + (size_t)b * Hn * Tn + (t0 + 2 * pr);
        const int hbase = grp << 8;
#pragma unroll 4
        for (int hh = 0; hh < 256; hh++) {
            int h = hbase + hh;
            const ulonglong2* wr2 = reinterpret_cast<const ulonglong2*>(wos + h * CDn);
            ulonglong2 wa = wr2[0], wb = wr2[1];
            float bo = bos[h];

            u64 a = ffma2(qp0[0], wa.x, 0ULL);
            a = ffma2(qp0[1], wa.y, a); a = ffma2(qp0[2], wb.x, a); a = ffma2(qp0[3], wb.y, a);
            float alo, ahi; unpack2(a, alo, ahi);
            float o0 = __fadd_rn(__fadd_rn(alo, ahi), bo);

            u64 c = ffma2(qp1[0], wa.x, 0ULL);
            c = ffma2(qp1[1], wa.y, c); c = ffma2(qp1[2], wb.x, c); c = ffma2(qp1[3], wb.y, c);
            float clo, chi; unpack2(c, clo, chi);
            float o1 = __fadd_rn(__fadd_rn(clo, chi), bo);

            __stcs(reinterpret_cast<float2*>(outbase + (size_t)h * Tn), make_float2(o0, o1));
        }
    }

    // ---- last block finalizes loss mean (whole block participates) ---------
    __syncthreads();
    if (tid == 0) {
        __threadfence();
        unsigned int c = atomicAdd(&g_count, 1u);
        s_is_last = (c == NBLK - 1) ? 1u : 0u;
        if (s_is_last) g_count = 0;
    }
    __syncthreads();
    if (s_is_last) {
        float v = __ldcg(g_losspart + tid) + __ldcg(g_losspart + tid + THREADS);
#pragma unroll
        for (int o = 16; o; o >>= 1) v += __shfl_xor_sync(0xFFFFFFFFu, v, o);
        __syncthreads();
        if ((tid & 31) == 0) sbestg[tid >> 5].x = v;
        __syncthreads();
        if (tid == 0) {
            float tot = 0.f;
#pragma unroll
            for (int w = 0; w < THREADS / 32; w++) tot += sbestg[w].x;
            float mean = tot * (1.0f / (float)(Bn * CDn * Tn));
            dout[LOSS_OFF]     = mean;
            dout[LOSS_OFF + 1] = mean;
        }
    }
}

// ---------------------------------------------------------------------------
extern "C" void kernel_launch(void* const* d_in, const int* in_sizes, int n_in,
                              void* d_out, int out_size) {
    const float* hid   = (const float*)d_in[0];
    const float* w_in  = (const float*)d_in[1];
    const float* b_in  = (const float*)d_in[2];
    const float* w_out = (const float*)d_in[3];
    const float* b_out = (const float*)d_in[4];
    const float* cb    = (const float*)d_in[5];
    float* dout = (float*)d_out;

    const int smem_bytes = SMEM_FLOATS * 4;  // 44576 B
    cudaFuncSetAttribute(main_kernel, cudaFuncAttributeMaxDynamicSharedMemorySize, smem_bytes);

    main_kernel<<<NBLK, THREADS, smem_bytes>>>(hid, w_in, b_in, w_out, b_out, cb, dout);
}